// round 7
// baseline (speedup 1.0000x reference)
#include <cuda_runtime.h>
#include <cstdint>

// Pipelined DCN CrossLayer:
//   cp.async.bulk (1D) streams 4-row x tiles into a 4-stage SMEM ring;
//   mbarrier expect_tx/complete_tx per stage. Compute is col-major
//   (thread t owns float4 column t; weights in registers), warp reduction
//   via 5-step SHFL butterfly over 12 partials (ILP), cross-warp combine
//   via tiny smem. Slot refill issued right after the __syncthreads that
//   ends all reads of that slot.

#define F_DIM   1024
#define NVEC    256
#define THREADS 256
#define NWARPS  8
#define TILE_R  4
#define STAGES  4
#define TILE_BYTES (TILE_R * F_DIM * 4)       // 16384
#define STAGE_V4   (TILE_R * NVEC)            // float4 per stage
#define GRID_TARGET 296                       // 2 CTAs x 148 SMs

__device__ __forceinline__ float dot4(float4 a, float4 b, float acc) {
    return fmaf(a.x, b.x, fmaf(a.y, b.y, fmaf(a.z, b.z, fmaf(a.w, b.w, acc))));
}
__device__ __forceinline__ uint32_t s2u(const void* p) {
    return (uint32_t)__cvta_generic_to_shared(p);
}
__device__ __forceinline__ void mbar_init(uint32_t a, uint32_t cnt) {
    asm volatile("mbarrier.init.shared::cta.b64 [%0], %1;" :: "r"(a), "r"(cnt) : "memory");
}
__device__ __forceinline__ void mbar_expect_tx(uint32_t a, uint32_t bytes) {
    asm volatile("mbarrier.arrive.expect_tx.shared::cta.b64 _, [%0], %1;"
                 :: "r"(a), "r"(bytes) : "memory");
}
__device__ __forceinline__ void mbar_wait(uint32_t a, uint32_t phase) {
    uint32_t done;
    asm volatile("{\n\t.reg .pred p;\n\t"
                 "mbarrier.try_wait.parity.acquire.cta.shared::cta.b64 p, [%1], %2;\n\t"
                 "selp.b32 %0, 1, 0, p;\n\t}"
                 : "=r"(done) : "r"(a), "r"(phase) : "memory");
    while (!done) {
        asm volatile("{\n\t.reg .pred p;\n\t"
                     "mbarrier.try_wait.parity.acquire.cta.shared::cta.b64 p, [%1], %2, 0x989680;\n\t"
                     "selp.b32 %0, 1, 0, p;\n\t}"
                     : "=r"(done) : "r"(a), "r"(phase) : "memory");
    }
}
__device__ __forceinline__ void bulk_g2s(uint32_t dst, const void* src,
                                         uint32_t bytes, uint32_t mbar) {
    asm volatile("cp.async.bulk.shared::cta.global.mbarrier::complete_tx::bytes "
                 "[%0], [%1], %2, [%3];"
                 :: "r"(dst), "l"(src), "r"(bytes), "r"(mbar) : "memory");
}

extern __shared__ float4 g_stage[];           // STAGES * STAGE_V4 float4

__global__ __launch_bounds__(THREADS)
void cross_bulk_kernel(const float* __restrict__ x,
                       const float* __restrict__ kernels,
                       const float* __restrict__ bias,
                       float* __restrict__ out,
                       int ntiles)
{
    __shared__ __align__(8) uint64_t full_bar[STAGES];
    __shared__ float red[2][12][NWARPS];

    const int t   = threadIdx.x;
    const int wid = t >> 5;
    const int lid = t & 31;

    uint32_t fbar[STAGES];
    #pragma unroll
    for (int s = 0; s < STAGES; s++) fbar[s] = s2u(&full_bar[s]);

    if (t == 0) {
        #pragma unroll
        for (int s = 0; s < STAGES; s++) mbar_init(fbar[s], 1);
        asm volatile("fence.proxy.async.shared::cta;" ::: "memory");
    }
    __syncthreads();

    // Tiles for this block: j = bid + m*grid, m = 0..nt-1
    const int bid  = blockIdx.x;
    const int grid = gridDim.x;
    const int nt   = (ntiles > bid) ? ((ntiles - bid - 1) / grid + 1) : 0;

    // Kick off the first STAGES copies immediately
    if (t == 0) {
        const int pre = (nt < STAGES) ? nt : STAGES;
        for (int k = 0; k < pre; k++) {
            mbar_expect_tx(fbar[k], TILE_BYTES);
            bulk_g2s(s2u(&g_stage[k * STAGE_V4]),
                     x + (size_t)(bid + (size_t)k * grid) * TILE_R * F_DIM,
                     TILE_BYTES, fbar[k]);
        }
    }

    // ---- Weights/bias into registers (overlaps with in-flight copies) ----
    const float4* __restrict__ k4 = reinterpret_cast<const float4*>(kernels);
    const float4* __restrict__ b4 = reinterpret_cast<const float4*>(bias);
    const float4 w0 = __ldg(&k4[t]);
    const float4 w1 = __ldg(&k4[NVEC + t]);
    const float4 w2 = __ldg(&k4[2 * NVEC + t]);
    const float4 b0 = __ldg(&b4[t]);
    const float4 b1 = __ldg(&b4[NVEC + t]);
    const float4 b2 = __ldg(&b4[2 * NVEC + t]);
    float4 bs;
    bs.x = b0.x + b1.x + b2.x;
    bs.y = b0.y + b1.y + b2.y;
    bs.z = b0.z + b1.z + b2.z;
    bs.w = b0.w + b1.w + b2.w;

    // c01 = b0.w1, c012 = (b0+b1).w2
    float c01, c012;
    {
        float pc01 = dot4(b0, w1, 0.f);
        float4 b01;
        b01.x = b0.x + b1.x; b01.y = b0.y + b1.y;
        b01.z = b0.z + b1.z; b01.w = b0.w + b1.w;
        float pc012 = dot4(b01, w2, 0.f);
        #pragma unroll
        for (int off = 16; off; off >>= 1) {
            pc01  += __shfl_xor_sync(0xFFFFFFFFu, pc01,  off);
            pc012 += __shfl_xor_sync(0xFFFFFFFFu, pc012, off);
        }
        if (lid == 0) { red[0][0][wid] = pc01; red[0][1][wid] = pc012; }
        __syncthreads();
        float a = 0.f, b = 0.f;
        #pragma unroll
        for (int i = 0; i < NWARPS; i++) { a += red[0][0][i]; b += red[0][1][i]; }
        c01 = a; c012 = b;
        __syncthreads();     // protect red[0] before loop reuses it
    }

    float4* __restrict__ o4 = reinterpret_cast<float4*>(out);

    #pragma unroll 1
    for (int m = 0; m < nt; ++m) {
        const int slot = m & (STAGES - 1);
        const uint32_t ph = (m >> 2) & 1;          // STAGES = 4
        mbar_wait(fbar[slot], ph);

        const float4* __restrict__ xs4 = g_stage + slot * STAGE_V4;

        // dot phase (all smem reads of this slot happen here)
        float4 xs[TILE_R];
        float  p[12];
        #pragma unroll
        for (int r = 0; r < TILE_R; r++) xs[r] = xs4[r * NVEC + t];
        #pragma unroll
        for (int r = 0; r < TILE_R; r++) {
            p[r]     = dot4(xs[r], w0, 0.f);
            p[4 + r] = dot4(xs[r], w1, 0.f);
            p[8 + r] = dot4(xs[r], w2, 0.f);
        }
        // 5-step butterfly over 12 independent partials (ILP hides SHFL lat)
        #pragma unroll
        for (int off = 16; off; off >>= 1) {
            #pragma unroll
            for (int j = 0; j < 12; j++)
                p[j] += __shfl_xor_sync(0xFFFFFFFFu, p[j], off);
        }

        const int buf = m & 1;
        if (lid == 0) {
            #pragma unroll
            for (int j = 0; j < 12; j++) red[buf][j][wid] = p[j];
        }
        __syncthreads();   // all reads of slot done; red[buf] published

        // refill this slot with tile m+STAGES (expect_tx arms next phase)
        if (t == 0 && m + STAGES < nt) {
            mbar_expect_tx(fbar[slot], TILE_BYTES);
            bulk_g2s(s2u(&g_stage[slot * STAGE_V4]),
                     x + (size_t)(bid + (size_t)(m + STAGES) * grid) * TILE_R * F_DIM,
                     TILE_BYTES, fbar[slot]);
        }

        // combine: sum 8 warps' partials (lanes 0..11), broadcast per row
        float val = 0.f;
        if (lid < 12) {
            #pragma unroll
            for (int w = 0; w < NWARPS; w++) val += red[buf][lid][w];
        }

        const size_t jtile = (size_t)bid + (size_t)m * grid;
        float4* __restrict__ orow = o4 + jtile * TILE_R * NVEC;
        #pragma unroll
        for (int r = 0; r < TILE_R; r++) {
            const float d0 = __shfl_sync(0xFFFFFFFFu, val, r);
            const float d1 = __shfl_sync(0xFFFFFFFFu, val, 4 + r);
            const float d2 = __shfl_sync(0xFFFFFFFFu, val, 8 + r);
            const float t1 = 1.f + d0;
            const float s1 = fmaf(t1, d1, c01);
            const float t2 = t1 + s1;
            const float s2 = fmaf(t2, d2, c012);
            const float a  = t2 + s2;
            float4 o;
            o.x = fmaf(a, xs[r].x, bs.x);
            o.y = fmaf(a, xs[r].y, bs.y);
            o.z = fmaf(a, xs[r].z, bs.z);
            o.w = fmaf(a, xs[r].w, bs.w);
            __stcs(&orow[r * NVEC + t], o);
        }
    }
}

extern "C" void kernel_launch(void* const* d_in, const int* in_sizes, int n_in,
                              void* d_out, int out_size)
{
    const float* x       = (const float*)d_in[0];
    const float* kernels = (const float*)d_in[1];
    const float* bias    = (const float*)d_in[2];
    float* out           = (float*)d_out;

    const int B = in_sizes[0] / F_DIM;
    const int ntiles = B / TILE_R;            // B = 16384 -> 4096 tiles
    const int grid = (ntiles < GRID_TARGET) ? ntiles : GRID_TARGET;

    cudaFuncSetAttribute(cross_bulk_kernel,
                         cudaFuncAttributeMaxDynamicSharedMemorySize,
                         STAGES * TILE_BYTES);
    cross_bulk_kernel<<<grid, THREADS, STAGES * TILE_BYTES>>>(
        x, kernels, bias, out, ntiles);
}